// round 4
// baseline (speedup 1.0000x reference)
#include <cuda_runtime.h>
#include <math.h>

// Problem constants (fixed shapes: x[131072,512], clusters[64,512], alpha scalar)
#define DDIM 512
#define KDIM 64
#define TILE_ROWS 128
#define CHUNK 32
#define NCHUNK (DDIM / CHUNK)   // 16
#define LDX 130                 // xs row pitch (floats): conflict-tuned, even for LDS.64
#define THREADS 256
#define MAXBLK 8192

// Scratch (no device mallocs allowed)
__device__ float g_cnT[DDIM * KDIM];     // normalized clusters, transposed [d][k]
__device__ float g_partial[MAXBLK];      // per-block loss partial sums

// ---------------------------------------------------------------------------
// Kernel 1: L2-normalize clusters, store transposed cT[d][k]
// ---------------------------------------------------------------------------
__global__ void norm_clusters_kernel(const float* __restrict__ clusters) {
    int k = blockIdx.x;          // 64 blocks
    int t = threadIdx.x;         // 128 threads
    float4 v = ((const float4*)(clusters + (size_t)k * DDIM))[t];  // 128*4 = 512
    float ss = v.x * v.x + v.y * v.y + v.z * v.z + v.w * v.w;
    #pragma unroll
    for (int o = 16; o; o >>= 1) ss += __shfl_xor_sync(0xffffffffu, ss, o);
    __shared__ float ws[4];
    __shared__ float s_inv;
    if ((t & 31) == 0) ws[t >> 5] = ss;
    __syncthreads();
    if (t == 0) {
        float s = ws[0] + ws[1] + ws[2] + ws[3];
        float n = sqrtf(s);
        s_inv = 1.0f / fmaxf(n, 1e-12f);
    }
    __syncthreads();
    float iv = s_inv;
    int d0 = t * 4;
    g_cnT[(d0 + 0) * KDIM + k] = v.x * iv;
    g_cnT[(d0 + 1) * KDIM + k] = v.y * iv;
    g_cnT[(d0 + 2) * KDIM + k] = v.z * iv;
    g_cnT[(d0 + 3) * KDIM + k] = v.w * iv;
}

// f32x2 packed FMA helpers (ptxas will not auto-fuse; must go through PTX)
__device__ __forceinline__ unsigned long long dup_f32x2(float v) {
    unsigned long long r;
    asm("mov.b64 %0, {%1, %1};" : "=l"(r) : "f"(v));
    return r;
}
__device__ __forceinline__ void fma_f32x2(unsigned long long& d,
                                          unsigned long long a,
                                          unsigned long long b) {
    asm("fma.rn.f32x2 %0, %1, %2, %0;" : "+l"(d) : "l"(a), "l"(b));
}

// ---------------------------------------------------------------------------
// Kernel 2: fused normalize(x) @ cT, softmax, probs store, loss partials
// Block tile: 128 rows x 64 cols. Thread (tx=t&15, ty=t>>4) owns
// rows ty*8..ty*8+7 (as 4 row-pairs in f32x2) and cols tx*4..tx*4+3.
// ---------------------------------------------------------------------------
__global__ __launch_bounds__(THREADS)
void cluster_main_kernel(const float* __restrict__ x,
                         const float* __restrict__ alphap,
                         float* __restrict__ out,
                         int loss_off, int store_probs) {
    __shared__ float xs[CHUNK][LDX];       // transposed x tile: xs[d][row]
    __shared__ float cs[CHUNK][KDIM];      // cT chunk: cs[d][k]
    __shared__ float norm2[TILE_ROWS];
    __shared__ float wred[THREADS / 32];

    const int t  = threadIdx.x;
    const int tx = t & 15;
    const int ty = t >> 4;
    const size_t row0 = (size_t)blockIdx.x * TILE_ROWS;

    unsigned long long acc[4][4];          // [row-pair m][col j]
    #pragma unroll
    for (int m = 0; m < 4; m++)
        #pragma unroll
        for (int j = 0; j < 4; j++) acc[m][j] = 0ull;

    // load mapping: pass p in 0..3, row = p*32 + (t>>3), dquad = (t&7)*4
    float psum[4] = {0.f, 0.f, 0.f, 0.f};
    const int lrow = t >> 3;               // 0..31
    const int ldq  = (t & 7) * 4;          // 0,4,...,28

    for (int c = 0; c < NCHUNK; c++) {
        __syncthreads();  // previous compute done before overwriting tiles
        // --- load cT chunk: 2048 floats = 512 float4 ---
        {
            const float4* gc = (const float4*)(g_cnT + c * CHUNK * KDIM);
            float4* cs4 = (float4*)cs;
            cs4[t]       = gc[t];
            cs4[t + 256] = gc[t + 256];
        }
        // --- load x chunk transposed, accumulate row sum-of-squares ---
        #pragma unroll
        for (int p = 0; p < 4; p++) {
            int r = p * 32 + lrow;
            float4 v = *(const float4*)(x + (row0 + r) * DDIM + c * CHUNK + ldq);
            psum[p] += v.x * v.x + v.y * v.y + v.z * v.z + v.w * v.w;
            xs[ldq + 0][r] = v.x;
            xs[ldq + 1][r] = v.y;
            xs[ldq + 2][r] = v.z;
            xs[ldq + 3][r] = v.w;
        }
        __syncthreads();
        // --- compute: per d, 16 FFMA2 = 32 FMAs per thread ---
        #pragma unroll 8
        for (int d = 0; d < CHUNK; d++) {
            float4 cv = *(const float4*)&cs[d][tx * 4];
            unsigned long long b0 = dup_f32x2(cv.x);
            unsigned long long b1 = dup_f32x2(cv.y);
            unsigned long long b2 = dup_f32x2(cv.z);
            unsigned long long b3 = dup_f32x2(cv.w);
            const float* xr = &xs[d][ty * 8];
            unsigned long long a0 = *(const unsigned long long*)(xr + 0);
            unsigned long long a1 = *(const unsigned long long*)(xr + 2);
            unsigned long long a2 = *(const unsigned long long*)(xr + 4);
            unsigned long long a3 = *(const unsigned long long*)(xr + 6);
            fma_f32x2(acc[0][0], a0, b0); fma_f32x2(acc[0][1], a0, b1);
            fma_f32x2(acc[0][2], a0, b2); fma_f32x2(acc[0][3], a0, b3);
            fma_f32x2(acc[1][0], a1, b0); fma_f32x2(acc[1][1], a1, b1);
            fma_f32x2(acc[1][2], a1, b2); fma_f32x2(acc[1][3], a1, b3);
            fma_f32x2(acc[2][0], a2, b0); fma_f32x2(acc[2][1], a2, b1);
            fma_f32x2(acc[2][2], a2, b2); fma_f32x2(acc[2][3], a2, b3);
            fma_f32x2(acc[3][0], a3, b0); fma_f32x2(acc[3][1], a3, b1);
            fma_f32x2(acc[3][2], a3, b2); fma_f32x2(acc[3][3], a3, b3);
        }
    }

    // --- finalize row norms: reduce psum over the 8 lanes sharing a row ---
    #pragma unroll
    for (int p = 0; p < 4; p++) {
        float v = psum[p];
        v += __shfl_xor_sync(0xffffffffu, v, 1);
        v += __shfl_xor_sync(0xffffffffu, v, 2);
        v += __shfl_xor_sync(0xffffffffu, v, 4);
        if ((t & 7) == 0) norm2[p * 32 + lrow] = v;
    }
    __syncthreads();

    const float alphav = *alphap;
    float lossacc = 0.f;

    // --- epilogue: per-row scale, softmax over K (16-lane groups), store ---
    #pragma unroll
    for (int m = 0; m < 4; m++) {
        #pragma unroll
        for (int h = 0; h < 2; h++) {
            int r = ty * 8 + 2 * m + h;
            float n2 = norm2[r];
            float inv = 1.0f / fmaxf(sqrtf(n2), 1e-12f);
            float s0, s1, s2, s3;
            {
                float2 u0 = *(float2*)&acc[m][0];
                float2 u1 = *(float2*)&acc[m][1];
                float2 u2 = *(float2*)&acc[m][2];
                float2 u3 = *(float2*)&acc[m][3];
                s0 = (h ? u0.y : u0.x) * inv;
                s1 = (h ? u1.y : u1.x) * inv;
                s2 = (h ? u2.y : u2.x) * inv;
                s3 = (h ? u3.y : u3.x) * inv;
            }
            float l0 = s0 * alphav, l1 = s1 * alphav, l2 = s2 * alphav, l3 = s3 * alphav;
            float mx = fmaxf(fmaxf(l0, l1), fmaxf(l2, l3));
            mx = fmaxf(mx, __shfl_xor_sync(0xffffffffu, mx, 1));
            mx = fmaxf(mx, __shfl_xor_sync(0xffffffffu, mx, 2));
            mx = fmaxf(mx, __shfl_xor_sync(0xffffffffu, mx, 4));
            mx = fmaxf(mx, __shfl_xor_sync(0xffffffffu, mx, 8));
            float e0 = __expf(l0 - mx), e1 = __expf(l1 - mx);
            float e2 = __expf(l2 - mx), e3 = __expf(l3 - mx);
            float es = e0 + e1 + e2 + e3;
            es += __shfl_xor_sync(0xffffffffu, es, 1);
            es += __shfl_xor_sync(0xffffffffu, es, 2);
            es += __shfl_xor_sync(0xffffffffu, es, 4);
            es += __shfl_xor_sync(0xffffffffu, es, 8);
            float rs = 1.0f / es;
            float p0 = e0 * rs, p1 = e1 * rs, p2 = e2 * rs, p3 = e3 * rs;
            float dloc = p0 * s0 + p1 * s1 + p2 * s2 + p3 * s3;
            dloc += __shfl_xor_sync(0xffffffffu, dloc, 1);
            dloc += __shfl_xor_sync(0xffffffffu, dloc, 2);
            dloc += __shfl_xor_sync(0xffffffffu, dloc, 4);
            dloc += __shfl_xor_sync(0xffffffffu, dloc, 8);
            if (tx == 0) lossacc += dloc;
            if (store_probs) {
                size_t ob = (size_t)loss_off + (row0 + r) * KDIM + tx * 4;
                out[ob + 0] = p0;
                out[ob + 1] = p1;
                out[ob + 2] = p2;
                out[ob + 3] = p3;
            }
        }
    }

    // --- deterministic block loss partial ---
    #pragma unroll
    for (int o = 16; o; o >>= 1) lossacc += __shfl_xor_sync(0xffffffffu, lossacc, o);
    if ((t & 31) == 0) wred[t >> 5] = lossacc;
    __syncthreads();
    if (t == 0) {
        float s = 0.f;
        #pragma unroll
        for (int w = 0; w < THREADS / 32; w++) s += wred[w];
        g_partial[blockIdx.x] = s;
    }
}

// ---------------------------------------------------------------------------
// Kernel 3: deterministic loss finalize
// ---------------------------------------------------------------------------
__global__ void finalize_kernel(float* __restrict__ out, int nblocks, int N,
                                int write_loss) {
    if (!write_loss) return;
    __shared__ float sm[256];
    float s = 0.f;
    for (int i = threadIdx.x; i < nblocks; i += 256) s += g_partial[i];
    sm[threadIdx.x] = s;
    __syncthreads();
    for (int o = 128; o; o >>= 1) {
        if (threadIdx.x < o) sm[threadIdx.x] += sm[threadIdx.x + o];
        __syncthreads();
    }
    if (threadIdx.x == 0) out[0] = -sm[0] / (float)N;
}

// ---------------------------------------------------------------------------
extern "C" void kernel_launch(void* const* d_in, const int* in_sizes, int n_in,
                              void* d_out, int out_size) {
    const float* x        = (const float*)d_in[0];
    const float* clusters = (const float*)d_in[1];
    const float* alpha    = (const float*)d_in[2];
    float* out = (float*)d_out;

    int N = in_sizes[0] / DDIM;           // 131072
    int nb = N / TILE_ROWS;               // 1024

    // Output layout: assume harness flattens (cluster_loss, cluster_probs)
    // in return order -> out[0]=loss, out[1:]=probs. Fallbacks for probs-only
    // or loss-only out_size values.
    long long nk = (long long)N * KDIM;
    int loss_off = 0, store_probs = 1, write_loss = 0;
    if ((long long)out_size == nk + 1) { loss_off = 1; write_loss = 1; }
    else if ((long long)out_size == nk) { loss_off = 0; write_loss = 0; }
    else { store_probs = 0; write_loss = 1; }   // scalar-only output

    norm_clusters_kernel<<<KDIM, 128>>>(clusters);
    cluster_main_kernel<<<nb, THREADS>>>(x, alpha, out, loss_off, store_probs);
    finalize_kernel<<<1, 256>>>(out, nb, N, write_loss);
}